// round 9
// baseline (speedup 1.0000x reference)
#include <cuda_runtime.h>
#include <cuda_bf16.h>
#include <cstdint>
#include <math.h>

#define EPS 1e-4f
#define B_SZ   64
#define C_SZ   512
#define HW_SZ  196
#define P_SZ   2000
#define MT     128
#define NT     112
#define KC     64
#define NSTAGE 8
#define NBUF   3
#define EPITCH 113

#define AP 144
#define BP 144
#define A_STG_B (MT*AP)                // 18432
#define B_STG_B (NT*BP)                // 16128
#define STG_B   (A_STG_B + B_STG_B)    // 34560
#define SMEM_BYTES (NBUF*STG_B)        // 103680

// global scratch (no cudaMalloc allowed); .bss zero-init
__device__ __nv_bfloat16 g_xb16t[B_SZ * HW_SZ * C_SZ];   // [b][hw][c]
__device__ __nv_bfloat16 g_pb16[2048 * C_SZ];            // [row][c], rows>=2000 zero
__device__ float g_x2[B_SZ * HW_SZ];
__device__ float g_p2[2048];

static __device__ __forceinline__ uint32_t s2u(const void* p) {
    uint32_t a;
    asm("{ .reg .u64 t; cvta.to.shared.u64 t, %1; cvt.u32.u64 %0, t; }"
        : "=r"(a) : "l"(p));
    return a;
}

static __device__ __forceinline__ void cpa16(uint32_t dst, const void* src, int sz) {
    asm volatile("cp.async.cg.shared.global [%0], [%1], 16, %2;"
                 :: "r"(dst), "l"(src), "r"(sz));
}

static __device__ __forceinline__ void ldsm4(uint32_t& r0, uint32_t& r1,
                                             uint32_t& r2, uint32_t& r3, uint32_t a) {
    asm volatile("ldmatrix.sync.aligned.m8n8.x4.shared.b16 {%0,%1,%2,%3}, [%4];"
                 : "=r"(r0), "=r"(r1), "=r"(r2), "=r"(r3) : "r"(a));
}

static __device__ __forceinline__ void ldsm2(uint32_t& r0, uint32_t& r1, uint32_t a) {
    asm volatile("ldmatrix.sync.aligned.m8n8.x2.shared.b16 {%0,%1}, [%2];"
                 : "=r"(r0), "=r"(r1) : "r"(a));
}

static __device__ __forceinline__ void mma_bf16(
    float& c0, float& c1, float& c2, float& c3,
    uint32_t a0, uint32_t a1, uint32_t a2, uint32_t a3,
    uint32_t b0, uint32_t b1)
{
    asm volatile(
        "mma.sync.aligned.m16n8k16.row.col.f32.bf16.bf16.f32 "
        "{%0,%1,%2,%3}, {%4,%5,%6,%7}, {%8,%9}, {%0,%1,%2,%3};"
        : "+f"(c0), "+f"(c1), "+f"(c2), "+f"(c3)
        : "r"(a0), "r"(a1), "r"(a2), "r"(a3), "r"(b0), "r"(b1));
}

// ---- prefix 1: x -> bf16 transposed [b][hw][c], + exact fp32 x2 ----
__global__ __launch_bounds__(256) void x_conv(const float* __restrict__ x) {
    __shared__ float sm[64 * 29];
    __shared__ float ps[28 * 65];
    const int tid = threadIdx.x;
    const int b   = blockIdx.y;
    const int hw0 = blockIdx.x * 28;
    const float* xb = x + (size_t)b * C_SZ * HW_SZ;
    __nv_bfloat16* ob = g_xb16t + ((size_t)b * HW_SZ + hw0) * C_SZ;

    for (int c0 = 0; c0 < C_SZ; c0 += 64) {
#pragma unroll
        for (int l = 0; l < 7; l++) {
            int idx = tid + l * 256;
            int c = idx / 28, hw = idx - c * 28;
            sm[c * 29 + hw] = xb[(size_t)(c0 + c) * HW_SZ + hw0 + hw];
        }
        __syncthreads();
#pragma unroll
        for (int l = 0; l < 7; l++) {
            int idx = tid + l * 256;
            int hw = idx >> 6, c = idx & 63;
            float v = sm[c * 29 + hw];
            ob[(size_t)hw * C_SZ + c0 + c] = __float2bfloat16(v);
            if (c0 == 0) ps[hw * 65 + c] = v * v;
            else         ps[hw * 65 + c] += v * v;
        }
        __syncthreads();
    }
    if (tid < 28) {
        float s = 0.f;
#pragma unroll
        for (int c = 0; c < 64; c++) s += ps[tid * 65 + c];
        g_x2[b * HW_SZ + hw0 + tid] = s;
    }
}

// ---- prefix 2: p -> bf16 + p2 ----
__global__ __launch_bounds__(256) void p_conv(const float* __restrict__ p) {
    int row  = blockIdx.x * 8 + (threadIdx.x >> 5);
    int lane = threadIdx.x & 31;
    float s = 0.f;
    if (row < P_SZ) {
        const float* pr = p + (size_t)row * C_SZ;
        __nv_bfloat16* pw = g_pb16 + (size_t)row * C_SZ;
#pragma unroll
        for (int t = lane; t < C_SZ; t += 32) {
            float v = pr[t];
            pw[t] = __float2bfloat16(v);
            s = fmaf(v, v, s);
        }
    }
#pragma unroll
    for (int o = 16; o > 0; o >>= 1)
        s += __shfl_down_sync(0xffffffffu, s, o);
    if (row < P_SZ && lane == 0) g_p2[row] = s;
}

// ---- main fused bf16 GEMM + epilogue ----
__global__ __launch_bounds__(256, 2) void proto_mma(
    const __nv_bfloat16* __restrict__ xt,
    const __nv_bfloat16* __restrict__ pb,
    float* __restrict__ out)
{
    extern __shared__ char smc[];
    const uint32_t sb = s2u(smc);
    const int tid  = threadIdx.x;
    const int wid  = tid >> 5;
    const int lane = tid & 31;
    const int qr   = lane >> 2;
    const int qc   = lane & 3;
    const int nb   = blockIdx.x * NT;
    const int mb   = blockIdx.y * MT;
    const int b    = blockIdx.z;
    const int mw   = (wid >> 1) * 32;
    const int nw   = (wid & 1) * 56;
    const int kst  = (wid & 1) << 1;          // warp-parity k-step stagger
    const __nv_bfloat16* xbase = xt + (size_t)b * HW_SZ * C_SZ;

    // ldmatrix lane address components
    const int lrow  = mw + (lane & 7) + 8 * ((lane >> 3) & 1);
    const int lcolB = (lane >> 4) << 4;
    const int brow  = nw + ((lane >> 4) << 3) + (lane & 7);
    const int bhalf = ((lane >> 3) & 1) << 4;

    const int a_row = tid >> 3, a_c = tid & 7;
    const __nv_bfloat16* a_src = pb + (size_t)(mb + a_row) * C_SZ + a_c * 8;

    float acc[2][7][4];
#pragma unroll
    for (int i = 0; i < 2; i++)
#pragma unroll
        for (int j = 0; j < 7; j++)
#pragma unroll
            for (int r = 0; r < 4; r++) acc[i][j][r] = 0.f;

    auto load_stage = [&](int s) {
        const int buf = s % NBUF;
        const int kt  = s * KC;
        const uint32_t sA = sb + buf * STG_B;
        const uint32_t sB = sA + A_STG_B;
#pragma unroll
        for (int l = 0; l < 4; l++) {
            cpa16(sA + (a_row + l * 32) * AP + a_c * 16,
                  a_src + (size_t)l * 32 * C_SZ + kt, 16);
        }
#pragma unroll
        for (int l = 0; l < 4; l++) {
            int idx = tid + l * 256;
            if (idx < 896) {
                int n = idx >> 3, c = idx & 7;
                int hw = nb + n;
                int sz = (hw < HW_SZ) ? 16 : 0;
                cpa16(sB + n * BP + c * 16,
                      xbase + (size_t)hw * C_SZ + kt + c * 8, sz);
            }
        }
    };

    load_stage(0);
    asm volatile("cp.async.commit_group;" ::: "memory");
    load_stage(1);
    asm volatile("cp.async.commit_group;" ::: "memory");

    for (int s = 0; s < NSTAGE; s++) {
        asm volatile("cp.async.wait_group 1;" ::: "memory");
        __syncthreads();
        if (s + 2 < NSTAGE) load_stage(s + 2);
        asm volatile("cp.async.commit_group;" ::: "memory");

        const int buf = s % NBUF;
        const uint32_t sA = sb + buf * STG_B;
        const uint32_t sB = sA + A_STG_B;
        const uint32_t aAddr = sA + lrow * AP + lcolB;
        const uint32_t bAddr = sB + brow * BP + bhalf;

        // hoist ALL A fragments for this stage (long-MLP burst, covered once)
        uint32_t afs[4][2][4];
#pragma unroll
        for (int ks = 0; ks < 4; ks++) {
            ldsm4(afs[ks][0][0], afs[ks][0][1], afs[ks][0][2], afs[ks][0][3],
                  aAddr + ks * 32);
            ldsm4(afs[ks][1][0], afs[ks][1][1], afs[ks][1][2], afs[ks][1][3],
                  aAddr + 16 * AP + ks * 32);
        }

#pragma unroll
        for (int jj = 0; jj < 4; jj++) {
            const int ks = (jj + kst) & 3;      // stagger LDS/MMA phases across warps
            const int ko = ks * 32;
            uint32_t bbf[7][2];
#pragma unroll
            for (int jp = 0; jp < 3; jp++)
                ldsm4(bbf[2*jp][0], bbf[2*jp][1], bbf[2*jp+1][0], bbf[2*jp+1][1],
                      bAddr + jp * 16 * BP + ko);
            ldsm2(bbf[6][0], bbf[6][1], bAddr + 48 * BP + ko);
#pragma unroll
            for (int j = 0; j < 7; j++) {
                mma_bf16(acc[0][j][0], acc[0][j][1], acc[0][j][2], acc[0][j][3],
                         afs[ks][0][0], afs[ks][0][1], afs[ks][0][2], afs[ks][0][3],
                         bbf[j][0], bbf[j][1]);
                mma_bf16(acc[1][j][0], acc[1][j][1], acc[1][j][2], acc[1][j][3],
                         afs[ks][1][0], afs[ks][1][1], afs[ks][1][2], afs[ks][1][3],
                         bbf[j][0], bbf[j][1]);
            }
        }
    }
    __syncthreads();   // compute done before epilogue reuses smem

    // ---- norms ----
    float pa2v[2][2];
#pragma unroll
    for (int i = 0; i < 2; i++)
#pragma unroll
        for (int h = 0; h < 2; h++) {
            int row = mb + mw + 16*i + 8*h + qr;
            pa2v[i][h] = (row < P_SZ) ? g_p2[row] : 0.f;
        }
    float x2v[7][2];
#pragma unroll
    for (int j = 0; j < 7; j++)
#pragma unroll
        for (int h = 0; h < 2; h++) {
            int n = nb + nw + 8*j + qc*2 + h;
            x2v[j][h] = (n < HW_SZ) ? g_x2[b * HW_SZ + n] : 0.f;
        }

    // ---- epilogue (fast log) -> smem transpose ----
    float* Es = (float*)smc;
#pragma unroll
    for (int i = 0; i < 2; i++)
#pragma unroll
        for (int j = 0; j < 7; j++)
#pragma unroll
            for (int r = 0; r < 4; r++) {
                int rl = mw + 16*i + qr + (r >> 1) * 8;
                int cl = nw + 8*j + qc * 2 + (r & 1);
                float dist = fmaxf(x2v[j][r & 1] - 2.f * acc[i][j][r] + pa2v[i][r >> 1], 0.f);
                Es[rl * EPITCH + cl] = __logf(__fdividef(dist + 1.0f, dist + EPS));
            }
    __syncthreads();

    // ---- coalesced store ----
    if (tid < 224) {
        const int col  = tid % NT;
        const int row0 = tid / NT;
        const int n    = nb + col;
        if (n < HW_SZ) {
#pragma unroll 4
            for (int row = row0; row < MT; row += 2) {
                int m = mb + row;
                if (m < P_SZ)
                    out[((size_t)b * P_SZ + m) * HW_SZ + n] = Es[row * EPITCH + col];
            }
        }
    }
}

extern "C" void kernel_launch(void* const* d_in, const int* in_sizes, int n_in,
                              void* d_out, int out_size) {
    const float* x = (const float*)d_in[0];   // (64, 512, 14, 14)
    const float* p = (const float*)d_in[1];   // (2000, 512, 1, 1)
    float* out = (float*)d_out;               // (64, 2000, 14, 14)

    x_conv<<<dim3(7, B_SZ), 256>>>(x);
    p_conv<<<250, 256>>>(p);

    __nv_bfloat16 *xt, *pb;
    cudaGetSymbolAddress((void**)&xt, g_xb16t);
    cudaGetSymbolAddress((void**)&pb, g_pb16);

    cudaFuncSetAttribute(proto_mma, cudaFuncAttributeMaxDynamicSharedMemorySize, SMEM_BYTES);
    dim3 grid(2, 16, B_SZ);
    proto_mma<<<grid, 256, SMEM_BYTES>>>(xt, pb, out);
}

// round 10
// speedup vs baseline: 1.2775x; 1.2775x over previous
#include <cuda_runtime.h>
#include <cuda_bf16.h>
#include <cstdint>
#include <math.h>

#define EPS 1e-4f
#define B_SZ   64
#define C_SZ   512
#define HW_SZ  196
#define P_SZ   2000
#define MT     128
#define NT     224              // 196 + 28 zero pad
#define KC     64
#define NSTAGE 8
#define NBUF   3
#define NTHR   512
#define EPITCH 225

#define AP 144
#define BP 144
#define A_STG_B (MT*AP)                // 18432
#define B_STG_B (NT*BP)                // 32256
#define STG_B   (A_STG_B + B_STG_B)    // 50688
#define SMEM_BYTES (NBUF*STG_B)        // 152064

// global scratch (no cudaMalloc allowed); .bss zero-init
__device__ __nv_bfloat16 g_xb16t[B_SZ * HW_SZ * C_SZ];   // [b][hw][c]
__device__ __nv_bfloat16 g_pb16[2048 * C_SZ];            // [row][c], rows>=2000 zero
__device__ float g_x2[B_SZ * HW_SZ];
__device__ float g_p2[2048];

static __device__ __forceinline__ uint32_t s2u(const void* p) {
    uint32_t a;
    asm("{ .reg .u64 t; cvta.to.shared.u64 t, %1; cvt.u32.u64 %0, t; }"
        : "=r"(a) : "l"(p));
    return a;
}

static __device__ __forceinline__ void cpa16(uint32_t dst, const void* src) {
    asm volatile("cp.async.cg.shared.global [%0], [%1], 16;"
                 :: "r"(dst), "l"(src));
}

static __device__ __forceinline__ void ldsm4(uint32_t& r0, uint32_t& r1,
                                             uint32_t& r2, uint32_t& r3, uint32_t a) {
    asm volatile("ldmatrix.sync.aligned.m8n8.x4.shared.b16 {%0,%1,%2,%3}, [%4];"
                 : "=r"(r0), "=r"(r1), "=r"(r2), "=r"(r3) : "r"(a));
}

static __device__ __forceinline__ void ldsm2(uint32_t& r0, uint32_t& r1, uint32_t a) {
    asm volatile("ldmatrix.sync.aligned.m8n8.x2.shared.b16 {%0,%1}, [%2];"
                 : "=r"(r0), "=r"(r1) : "r"(a));
}

static __device__ __forceinline__ void mma_bf16(
    float& c0, float& c1, float& c2, float& c3,
    uint32_t a0, uint32_t a1, uint32_t a2, uint32_t a3,
    uint32_t b0, uint32_t b1)
{
    asm volatile(
        "mma.sync.aligned.m16n8k16.row.col.f32.bf16.bf16.f32 "
        "{%0,%1,%2,%3}, {%4,%5,%6,%7}, {%8,%9}, {%0,%1,%2,%3};"
        : "+f"(c0), "+f"(c1), "+f"(c2), "+f"(c3)
        : "r"(a0), "r"(a1), "r"(a2), "r"(a3), "r"(b0), "r"(b1));
}

// ---- prefix 1: x -> bf16 transposed [b][hw][c], + exact fp32 x2 ----
__global__ __launch_bounds__(256) void x_conv(const float* __restrict__ x) {
    __shared__ float sm[64 * 29];
    __shared__ float ps[28 * 65];
    const int tid = threadIdx.x;
    const int b   = blockIdx.y;
    const int hw0 = blockIdx.x * 28;
    const float* xb = x + (size_t)b * C_SZ * HW_SZ;
    __nv_bfloat16* ob = g_xb16t + ((size_t)b * HW_SZ + hw0) * C_SZ;

    for (int c0 = 0; c0 < C_SZ; c0 += 64) {
#pragma unroll
        for (int l = 0; l < 7; l++) {
            int idx = tid + l * 256;
            int c = idx / 28, hw = idx - c * 28;
            sm[c * 29 + hw] = xb[(size_t)(c0 + c) * HW_SZ + hw0 + hw];
        }
        __syncthreads();
#pragma unroll
        for (int l = 0; l < 7; l++) {
            int idx = tid + l * 256;
            int hw = idx >> 6, c = idx & 63;
            float v = sm[c * 29 + hw];
            ob[(size_t)hw * C_SZ + c0 + c] = __float2bfloat16(v);
            if (c0 == 0) ps[hw * 65 + c] = v * v;
            else         ps[hw * 65 + c] += v * v;
        }
        __syncthreads();
    }
    if (tid < 28) {
        float s = 0.f;
#pragma unroll
        for (int c = 0; c < 64; c++) s += ps[tid * 65 + c];
        g_x2[b * HW_SZ + hw0 + tid] = s;
    }
}

// ---- prefix 2: p -> bf16 + p2 ----
__global__ __launch_bounds__(256) void p_conv(const float* __restrict__ p) {
    int row  = blockIdx.x * 8 + (threadIdx.x >> 5);
    int lane = threadIdx.x & 31;
    float s = 0.f;
    if (row < P_SZ) {
        const float* pr = p + (size_t)row * C_SZ;
        __nv_bfloat16* pw = g_pb16 + (size_t)row * C_SZ;
#pragma unroll
        for (int t = lane; t < C_SZ; t += 32) {
            float v = pr[t];
            pw[t] = __float2bfloat16(v);
            s = fmaf(v, v, s);
        }
    }
#pragma unroll
    for (int o = 16; o > 0; o >>= 1)
        s += __shfl_down_sync(0xffffffffu, s, o);
    if (row < P_SZ && lane == 0) g_p2[row] = s;
}

// ---- main fused bf16 GEMM + epilogue (512 threads, full 196-n tile) ----
__global__ __launch_bounds__(NTHR, 1) void proto_mma(
    const __nv_bfloat16* __restrict__ xt,
    const __nv_bfloat16* __restrict__ pb,
    float* __restrict__ out)
{
    extern __shared__ char smc[];
    const uint32_t sb = s2u(smc);
    const int tid  = threadIdx.x;
    const int wid  = tid >> 5;
    const int lane = tid & 31;
    const int qr   = lane >> 2;
    const int qc   = lane & 3;
    const int mb   = blockIdx.x * MT;
    const int b    = blockIdx.y;
    const int mw   = (wid >> 2) * 32;     // 4 m-groups
    const int nw   = (wid & 3) * 56;      // 4 n-groups (224 cols)
    const __nv_bfloat16* xbase = xt + (size_t)b * HW_SZ * C_SZ;

    // ldmatrix lane address components
    const int lrow  = mw + (lane & 7) + 8 * ((lane >> 3) & 1);
    const int lcolB = (lane >> 4) << 4;
    const int brow  = nw + ((lane >> 4) << 3) + (lane & 7);
    const int bhalf = ((lane >> 3) & 1) << 4;

    // loader coords
    const int a_row = tid >> 3, a_c = tid & 7;       // rows a_row, a_row+64
    const __nv_bfloat16* a_src = pb + (size_t)(mb + a_row) * C_SZ + a_c * 8;

    // pre-zero B pad rows (196..223) of all buffers; loader never writes them
    for (int i = tid; i < NBUF * 28 * 32; i += NTHR) {
        int buf = i / (28 * 32), r = i % (28 * 32);
        *(float*)(smc + buf * STG_B + A_STG_B + 196 * BP + (r >> 5) * BP + (r & 31) * 4) = 0.f;
    }

    float acc[2][7][4];
#pragma unroll
    for (int i = 0; i < 2; i++)
#pragma unroll
        for (int j = 0; j < 7; j++)
#pragma unroll
            for (int r = 0; r < 4; r++) acc[i][j][r] = 0.f;

    auto load_stage = [&](int s) {
        const int buf = s % NBUF;
        const int kt  = s * KC;
        const uint32_t sA = sb + buf * STG_B;
        const uint32_t sB = sA + A_STG_B;
        // A: 128 rows x 8 chunks = 1024, 2/thread
        cpa16(sA + a_row * AP + a_c * 16, a_src + kt);
        cpa16(sA + (a_row + 64) * AP + a_c * 16, a_src + (size_t)64 * C_SZ + kt);
        // B: 196 rows x 8 chunks = 1568 = 3*512 + 32
#pragma unroll
        for (int l = 0; l < 3; l++) {
            int idx = tid + l * NTHR;
            int n = idx >> 3, c = idx & 7;
            cpa16(sB + n * BP + c * 16, xbase + (size_t)n * C_SZ + kt + c * 8);
        }
        if (tid < 32) {
            int idx = tid + 1536;
            int n = idx >> 3, c = idx & 7;
            cpa16(sB + n * BP + c * 16, xbase + (size_t)n * C_SZ + kt + c * 8);
        }
    };

    load_stage(0);
    asm volatile("cp.async.commit_group;" ::: "memory");
    load_stage(1);
    asm volatile("cp.async.commit_group;" ::: "memory");

    for (int s = 0; s < NSTAGE; s++) {
        asm volatile("cp.async.wait_group 1;" ::: "memory");
        __syncthreads();
        if (s + 2 < NSTAGE) load_stage(s + 2);
        asm volatile("cp.async.commit_group;" ::: "memory");

        const int buf = s % NBUF;
        const uint32_t sA = sb + buf * STG_B;
        const uint32_t sB = sA + A_STG_B;
        const uint32_t aAddr = sA + lrow * AP + lcolB;
        const uint32_t bAddr = sB + brow * BP + bhalf;

#pragma unroll
        for (int ks = 0; ks < 4; ks++) {
            const int ko = ks * 32;
            uint32_t af[2][4];
            ldsm4(af[0][0], af[0][1], af[0][2], af[0][3], aAddr + ko);
            ldsm4(af[1][0], af[1][1], af[1][2], af[1][3], aAddr + 16 * AP + ko);
            uint32_t bbf[7][2];
#pragma unroll
            for (int jp = 0; jp < 3; jp++)
                ldsm4(bbf[2*jp][0], bbf[2*jp][1], bbf[2*jp+1][0], bbf[2*jp+1][1],
                      bAddr + jp * 16 * BP + ko);
            ldsm2(bbf[6][0], bbf[6][1], bAddr + 48 * BP + ko);
#pragma unroll
            for (int j = 0; j < 7; j++) {
                mma_bf16(acc[0][j][0], acc[0][j][1], acc[0][j][2], acc[0][j][3],
                         af[0][0], af[0][1], af[0][2], af[0][3], bbf[j][0], bbf[j][1]);
                mma_bf16(acc[1][j][0], acc[1][j][1], acc[1][j][2], acc[1][j][3],
                         af[1][0], af[1][1], af[1][2], af[1][3], bbf[j][0], bbf[j][1]);
            }
        }
    }
    __syncthreads();   // compute done before epilogue reuses smem

    // ---- norms ----
    float pa2v[2][2];
#pragma unroll
    for (int i = 0; i < 2; i++)
#pragma unroll
        for (int h = 0; h < 2; h++) {
            int row = mb + mw + 16*i + 8*h + qr;
            pa2v[i][h] = (row < P_SZ) ? g_p2[row] : 0.f;
        }
    float x2v[7][2];
#pragma unroll
    for (int j = 0; j < 7; j++)
#pragma unroll
        for (int h = 0; h < 2; h++) {
            int n = nw + 8*j + qc*2 + h;
            x2v[j][h] = (n < HW_SZ) ? g_x2[b * HW_SZ + n] : 0.f;
        }

    // ---- epilogue (fast log) -> smem transpose ----
    float* Es = (float*)smc;   // 128 x 225 fp32 = 115200 <= 152064
#pragma unroll
    for (int i = 0; i < 2; i++)
#pragma unroll
        for (int j = 0; j < 7; j++)
#pragma unroll
            for (int r = 0; r < 4; r++) {
                int rl = mw + 16*i + qr + (r >> 1) * 8;
                int cl = nw + 8*j + qc * 2 + (r & 1);
                float dist = fmaxf(x2v[j][r & 1] - 2.f * acc[i][j][r] + pa2v[i][r >> 1], 0.f);
                Es[rl * EPITCH + cl] = __logf(__fdividef(dist + 1.0f, dist + EPS));
            }
    __syncthreads();

    // ---- coalesced store (196-contig columns) ----
    if (tid < 392) {
        const int col  = tid % HW_SZ;
        const int row0 = tid / HW_SZ;
        float* ob = out + ((size_t)b * P_SZ + mb) * HW_SZ + col;
#pragma unroll 4
        for (int row = row0; row < MT; row += 2) {
            if (mb + row < P_SZ)
                ob[(size_t)row * HW_SZ] = Es[row * EPITCH + col];
        }
    }
}

extern "C" void kernel_launch(void* const* d_in, const int* in_sizes, int n_in,
                              void* d_out, int out_size) {
    const float* x = (const float*)d_in[0];   // (64, 512, 14, 14)
    const float* p = (const float*)d_in[1];   // (2000, 512, 1, 1)
    float* out = (float*)d_out;               // (64, 2000, 14, 14)

    x_conv<<<dim3(7, B_SZ), 256>>>(x);
    p_conv<<<250, 256>>>(p);

    __nv_bfloat16 *xt, *pb;
    cudaGetSymbolAddress((void**)&xt, g_xb16t);
    cudaGetSymbolAddress((void**)&pb, g_pb16);

    cudaFuncSetAttribute(proto_mma, cudaFuncAttributeMaxDynamicSharedMemorySize, SMEM_BYTES);
    dim3 grid(16, B_SZ);
    proto_mma<<<grid, NTHR, SMEM_BYTES>>>(xt, pb, out);
}

// round 11
// speedup vs baseline: 1.3031x; 1.0200x over previous
#include <cuda_runtime.h>
#include <cuda_bf16.h>
#include <cstdint>
#include <math.h>

#define EPS 1e-4f
#define B_SZ   64
#define C_SZ   512
#define HW_SZ  196
#define P_SZ   2000
#define MT     128
#define NT     224              // 196 + 28 zero pad
#define KC     128
#define NSTAGE 4
#define NBUF   2
#define NTHR   512
#define EPITCH 225

#define AP 272                         // row pitch bytes (256B data + 16 pad)
#define BP 272
#define A_STG_B (MT*AP)                // 34816
#define B_STG_B (NT*BP)                // 60928
#define STG_B   (A_STG_B + B_STG_B)    // 95744
#define SMEM_BYTES (NBUF*STG_B)        // 191488

// global scratch (no cudaMalloc allowed); .bss zero-init
__device__ __nv_bfloat16 g_xb16t[B_SZ * HW_SZ * C_SZ];   // [b][hw][c]
__device__ __nv_bfloat16 g_pb16[2048 * C_SZ];            // [row][c], rows>=2000 zero
__device__ float g_x2[B_SZ * HW_SZ];
__device__ float g_p2[2048];

static __device__ __forceinline__ uint32_t s2u(const void* p) {
    uint32_t a;
    asm("{ .reg .u64 t; cvta.to.shared.u64 t, %1; cvt.u32.u64 %0, t; }"
        : "=r"(a) : "l"(p));
    return a;
}

static __device__ __forceinline__ void cpa16(uint32_t dst, const void* src) {
    asm volatile("cp.async.cg.shared.global [%0], [%1], 16;"
                 :: "r"(dst), "l"(src));
}

static __device__ __forceinline__ void ldsm4(uint32_t& r0, uint32_t& r1,
                                             uint32_t& r2, uint32_t& r3, uint32_t a) {
    asm volatile("ldmatrix.sync.aligned.m8n8.x4.shared.b16 {%0,%1,%2,%3}, [%4];"
                 : "=r"(r0), "=r"(r1), "=r"(r2), "=r"(r3) : "r"(a));
}

static __device__ __forceinline__ void ldsm2(uint32_t& r0, uint32_t& r1, uint32_t a) {
    asm volatile("ldmatrix.sync.aligned.m8n8.x2.shared.b16 {%0,%1}, [%2];"
                 : "=r"(r0), "=r"(r1) : "r"(a));
}

static __device__ __forceinline__ void mma_bf16(
    float& c0, float& c1, float& c2, float& c3,
    uint32_t a0, uint32_t a1, uint32_t a2, uint32_t a3,
    uint32_t b0, uint32_t b1)
{
    asm volatile(
        "mma.sync.aligned.m16n8k16.row.col.f32.bf16.bf16.f32 "
        "{%0,%1,%2,%3}, {%4,%5,%6,%7}, {%8,%9}, {%0,%1,%2,%3};"
        : "+f"(c0), "+f"(c1), "+f"(c2), "+f"(c3)
        : "r"(a0), "r"(a1), "r"(a2), "r"(a3), "r"(b0), "r"(b1));
}

// ---- merged prefix: blocks [0,448) transpose+convert x & x2; [448,698) convert p & p2 ----
__global__ __launch_bounds__(256) void prefix_k(const float* __restrict__ x,
                                                const float* __restrict__ p) {
    __shared__ float sm[128 * 29];      // [c][hw] chunk
    __shared__ float ps[28 * 130];      // per-(hw,c) square partials
    const int tid = threadIdx.x;

    if (blockIdx.x < 448) {
        const int b   = blockIdx.x >> 3;          // 448 = 64 b * 7 hw-tiles? -> use /7 mapping
        // NOTE: 448 = 64*7; map: b = blockIdx.x / 7, tile = blockIdx.x % 7
        const int bb  = blockIdx.x / 7;
        const int hw0 = (blockIdx.x % 7) * 28;
        (void)b;
        const float* xb = x + (size_t)bb * C_SZ * HW_SZ;
        __nv_bfloat16* ob = g_xb16t + ((size_t)bb * HW_SZ + hw0) * C_SZ;

        for (int c0 = 0; c0 < C_SZ; c0 += 128) {
#pragma unroll
            for (int l = 0; l < 14; l++) {
                int idx = tid + l * 256;
                int c = idx / 28, hw = idx - c * 28;
                sm[c * 29 + hw] = xb[(size_t)(c0 + c) * HW_SZ + hw0 + hw];
            }
            __syncthreads();
#pragma unroll
            for (int l = 0; l < 14; l++) {
                int idx = tid + l * 256;
                int hw = idx >> 7, c = idx & 127;
                float v = sm[c * 29 + hw];
                ob[(size_t)hw * C_SZ + c0 + c] = __float2bfloat16(v);
                if (c0 == 0) ps[hw * 130 + c] = v * v;
                else         ps[hw * 130 + c] += v * v;
            }
            __syncthreads();
        }
        if (tid < 28) {
            float s = 0.f;
#pragma unroll
            for (int c = 0; c < 128; c++) s += ps[tid * 130 + c];
            g_x2[bb * HW_SZ + hw0 + tid] = s;
        }
    } else {
        int row  = (blockIdx.x - 448) * 8 + (tid >> 5);
        int lane = tid & 31;
        float s = 0.f;
        if (row < P_SZ) {
            const float* pr = p + (size_t)row * C_SZ;
            __nv_bfloat16* pw = g_pb16 + (size_t)row * C_SZ;
#pragma unroll
            for (int t = lane; t < C_SZ; t += 32) {
                float v = pr[t];
                pw[t] = __float2bfloat16(v);
                s = fmaf(v, v, s);
            }
        }
#pragma unroll
        for (int o = 16; o > 0; o >>= 1)
            s += __shfl_down_sync(0xffffffffu, s, o);
        if (row < P_SZ && lane == 0) g_p2[row] = s;
    }
}

// ---- main fused bf16 GEMM + epilogue (512 threads, KC=128, double buffer) ----
__global__ __launch_bounds__(NTHR, 1) void proto_mma(
    const __nv_bfloat16* __restrict__ xt,
    const __nv_bfloat16* __restrict__ pb,
    float* __restrict__ out)
{
    extern __shared__ char smc[];
    const uint32_t sb = s2u(smc);
    const int tid  = threadIdx.x;
    const int wid  = tid >> 5;
    const int lane = tid & 31;
    const int qr   = lane >> 2;
    const int qc   = lane & 3;
    const int mb   = blockIdx.x * MT;
    const int b    = blockIdx.y;
    const int mw   = (wid >> 2) * 32;
    const int nw   = (wid & 3) * 56;
    const __nv_bfloat16* xbase = xt + (size_t)b * HW_SZ * C_SZ;

    // ldmatrix lane address components
    const int lrow  = mw + (lane & 7) + 8 * ((lane >> 3) & 1);
    const int lcolB = (lane >> 4) << 4;
    const int brow  = nw + ((lane >> 4) << 3) + (lane & 7);
    const int bhalf = ((lane >> 3) & 1) << 4;

    // loader coords: 16 chunks/row
    const int a_row = tid >> 4, a_c = tid & 15;
    const __nv_bfloat16* a_src = pb + (size_t)(mb + a_row) * C_SZ + a_c * 8;

    // pre-zero B pad rows (196..223) of both buffers
    for (int i = tid; i < NBUF * 28 * 68; i += NTHR) {
        int buf = i / (28 * 68), r = i % (28 * 68);
        *(float*)(smc + buf * STG_B + A_STG_B + (196 + r / 68) * BP + (r % 68) * 4) = 0.f;
    }

    float acc[2][7][4];
#pragma unroll
    for (int i = 0; i < 2; i++)
#pragma unroll
        for (int j = 0; j < 7; j++)
#pragma unroll
            for (int r = 0; r < 4; r++) acc[i][j][r] = 0.f;

    auto load_stage = [&](int s) {
        const int buf = s & 1;
        const int kt  = s * KC;
        const uint32_t sA = sb + buf * STG_B;
        const uint32_t sB = sA + A_STG_B;
        // A: 128 rows x 16 chunks = 2048, 4/thread (rows step 32)
#pragma unroll
        for (int l = 0; l < 4; l++) {
            cpa16(sA + (a_row + l * 32) * AP + a_c * 16,
                  a_src + (size_t)l * 32 * C_SZ + kt);
        }
        // B: 196 rows x 16 chunks = 3136 = 6*512 + 64
#pragma unroll
        for (int l = 0; l < 6; l++) {
            int idx = tid + l * NTHR;
            int n = idx >> 4, c = idx & 15;
            cpa16(sB + n * BP + c * 16, xbase + (size_t)n * C_SZ + kt + c * 8);
        }
        if (tid < 64) {
            int idx = tid + 3072;
            int n = idx >> 4, c = idx & 15;
            cpa16(sB + n * BP + c * 16, xbase + (size_t)n * C_SZ + kt + c * 8);
        }
    };

    load_stage(0);
    asm volatile("cp.async.commit_group;" ::: "memory");

    for (int s = 0; s < NSTAGE; s++) {
        __syncthreads();                      // prev compute done before buffer overwrite
        if (s + 1 < NSTAGE) {
            load_stage(s + 1);
            asm volatile("cp.async.commit_group;" ::: "memory");
            asm volatile("cp.async.wait_group 1;" ::: "memory");
        } else {
            asm volatile("cp.async.wait_group 0;" ::: "memory");
        }
        __syncthreads();                      // stage s data visible to all warps

        const int buf = s & 1;
        const uint32_t sA = sb + buf * STG_B;
        const uint32_t sB = sA + A_STG_B;
        const uint32_t aAddr = sA + lrow * AP + lcolB;
        const uint32_t bAddr = sB + brow * BP + bhalf;

#pragma unroll
        for (int ks = 0; ks < 8; ks++) {
            const int ko = ks * 32;
            uint32_t af[2][4];
            ldsm4(af[0][0], af[0][1], af[0][2], af[0][3], aAddr + ko);
            ldsm4(af[1][0], af[1][1], af[1][2], af[1][3], aAddr + 16 * AP + ko);
            uint32_t bbf[7][2];
#pragma unroll
            for (int jp = 0; jp < 3; jp++)
                ldsm4(bbf[2*jp][0], bbf[2*jp][1], bbf[2*jp+1][0], bbf[2*jp+1][1],
                      bAddr + jp * 16 * BP + ko);
            ldsm2(bbf[6][0], bbf[6][1], bAddr + 48 * BP + ko);
#pragma unroll
            for (int j = 0; j < 7; j++) {
                mma_bf16(acc[0][j][0], acc[0][j][1], acc[0][j][2], acc[0][j][3],
                         af[0][0], af[0][1], af[0][2], af[0][3], bbf[j][0], bbf[j][1]);
                mma_bf16(acc[1][j][0], acc[1][j][1], acc[1][j][2], acc[1][j][3],
                         af[1][0], af[1][1], af[1][2], af[1][3], bbf[j][0], bbf[j][1]);
            }
        }
    }
    __syncthreads();   // compute done before epilogue reuses smem

    // ---- norms ----
    float pa2v[2][2];
#pragma unroll
    for (int i = 0; i < 2; i++)
#pragma unroll
        for (int h = 0; h < 2; h++) {
            int row = mb + mw + 16*i + 8*h + qr;
            pa2v[i][h] = (row < P_SZ) ? g_p2[row] : 0.f;
        }
    float x2v[7][2];
#pragma unroll
    for (int j = 0; j < 7; j++)
#pragma unroll
        for (int h = 0; h < 2; h++) {
            int n = nw + 8*j + qc*2 + h;
            x2v[j][h] = (n < HW_SZ) ? g_x2[b * HW_SZ + n] : 0.f;
        }

    // ---- epilogue (fast log) -> smem transpose ----
    float* Es = (float*)smc;   // 128 x 225 fp32 = 115200 <= 191488
#pragma unroll
    for (int i = 0; i < 2; i++)
#pragma unroll
        for (int j = 0; j < 7; j++)
#pragma unroll
            for (int r = 0; r < 4; r++) {
                int rl = mw + 16*i + qr + (r >> 1) * 8;
                int cl = nw + 8*j + qc * 2 + (r & 1);
                float dist = fmaxf(x2v[j][r & 1] - 2.f * acc[i][j][r] + pa2v[i][r >> 1], 0.f);
                Es[rl * EPITCH + cl] = __logf(__fdividef(dist + 1.0f, dist + EPS));
            }
    __syncthreads();

    // ---- coalesced store ----
    if (tid < 392) {
        const int col  = tid % HW_SZ;
        const int row0 = tid / HW_SZ;
        float* ob = out + ((size_t)b * P_SZ + mb) * HW_SZ + col;
#pragma unroll 4
        for (int row = row0; row < MT; row += 2) {
            if (mb + row < P_SZ)
                ob[(size_t)row * HW_SZ] = Es[row * EPITCH + col];
        }
    }
}

extern "C" void kernel_launch(void* const* d_in, const int* in_sizes, int n_in,
                              void* d_out, int out_size) {
    const float* x = (const float*)d_in[0];   // (64, 512, 14, 14)
    const float* p = (const float*)d_in[1];   // (2000, 512, 1, 1)
    float* out = (float*)d_out;               // (64, 2000, 14, 14)

    prefix_k<<<698, 256>>>(x, p);

    __nv_bfloat16 *xt, *pb;
    cudaGetSymbolAddress((void**)&xt, g_xb16t);
    cudaGetSymbolAddress((void**)&pb, g_pb16);

    cudaFuncSetAttribute(proto_mma, cudaFuncAttributeMaxDynamicSharedMemorySize, SMEM_BYTES);
    dim3 grid(16, B_SZ);
    proto_mma<<<grid, NTHR, SMEM_BYTES>>>(xt, pb, out);
}